// round 2
// baseline (speedup 1.0000x reference)
#include <cuda_runtime.h>
#include <cuda_bf16.h>

// ---------------------------------------------------------------------------
// CascadedAttention: B=128, T=75, D=512, V=28
//
// Kernel 1 (prologue): per-batch GEMM  [75,512] @ [512, 512+84+28]
//     scratch[b][t][0:512]   = x@Ua + Ba2          (UaH)
//     scratch[b][t][512:596] = x@gru_kernel + gb0  (XG', gb0 folded: sum(sm)=1)
//     scratch[b][t][596:624] = x@Co                (XC)
// Kernel 2 (recurrence): 1 CTA per batch row, everything smem-resident,
//     75 sequential steps of attention + GRU + output softmax.
// ---------------------------------------------------------------------------

#define B_  128
#define T_  75
#define D_  512
#define V_  28
#define NC  624
#define PT  (T_*NC)          // 46800 floats per batch row

__device__ float g_scr[B_ * PT];   // 23.96 MB static scratch (no allocation)

__device__ __forceinline__ float ex2f(float x){ float y; asm("ex2.approx.f32 %0, %1;" : "=f"(y) : "f"(x)); return y; }
__device__ __forceinline__ float rcpf(float x){ float y; asm("rcp.approx.f32 %0, %1;" : "=f"(y) : "f"(x)); return y; }
#define L2E 1.4426950408889634f
__device__ __forceinline__ float fast_tanh(float x){ return fmaf(-2.0f, rcpf(ex2f(x * (2.0f * L2E)) + 1.0f), 1.0f); }
__device__ __forceinline__ float fast_sig (float x){ return rcpf(1.0f + ex2f(-x * L2E)); }

// ---------------------------------------------------------------------------
// Prologue GEMM. grid (128, 3), 256 threads = 32 tx * 8 ty.
//   part 0: Ua cols [  0,256)   TM=10, TN=8
//   part 1: Ua cols [256,512)   TM=10, TN=8
//   part 2: gru_kernel (84) + Co (28), TM=10, TN=4
// x[75][512] staged in smem (padded to 80 rows); per-warp LDS is broadcast
// (ty uniform within warp) -> conflict-free.
// ---------------------------------------------------------------------------
__global__ void __launch_bounds__(256)
prologue_kernel(const float* __restrict__ x,
                const float* __restrict__ Ua,
                const float* __restrict__ gk,
                const float* __restrict__ Co,
                const float* __restrict__ Ba2,
                const float* __restrict__ gbias)
{
    extern __shared__ float xs[];          // [80][512]
    const int b    = blockIdx.x;
    const int part = blockIdx.y;
    const int tid  = threadIdx.x;
    const int tx   = tid & 31;
    const int ty   = tid >> 5;

    // stage x[b] into smem (float4 coalesced)
    const float4* xb = reinterpret_cast<const float4*>(x + (long)b * T_ * D_);
    for (int i = tid; i < T_ * (D_/4); i += 256) {
        float4 v = xb[i];
        int t = i >> 7;                // 128 float4 per row
        int k = (i & 127) << 2;
        float* d = &xs[t * D_ + k];
        d[0]=v.x; d[1]=v.y; d[2]=v.z; d[3]=v.w;
    }
    // zero pad rows 75..79 (read by out-of-range row lanes, results discarded)
    for (int i = tid; i < 5 * D_; i += 256) xs[T_ * D_ + i] = 0.0f;
    __syncthreads();

    float* outb = g_scr + (long)b * PT;

    if (part < 2) {
        const int col = part * 256 + 4 * tx;         // cols col..col+3 and col+128..col+131
        float acc[10][8];
        #pragma unroll
        for (int i = 0; i < 10; i++) {
            #pragma unroll
            for (int j = 0; j < 4; j++) { acc[i][j] = Ba2[col + j]; acc[i][4+j] = Ba2[col + 128 + j]; }
        }
        #pragma unroll 2
        for (int k = 0; k < D_; k++) {
            float4 w0 = *reinterpret_cast<const float4*>(&Ua[k * D_ + col]);
            float4 w1 = *reinterpret_cast<const float4*>(&Ua[k * D_ + col + 128]);
            float xm[10];
            #pragma unroll
            for (int i = 0; i < 10; i++) xm[i] = xs[(ty + 8*i) * D_ + k];
            #pragma unroll
            for (int i = 0; i < 10; i++) {
                acc[i][0] = fmaf(xm[i], w0.x, acc[i][0]);
                acc[i][1] = fmaf(xm[i], w0.y, acc[i][1]);
                acc[i][2] = fmaf(xm[i], w0.z, acc[i][2]);
                acc[i][3] = fmaf(xm[i], w0.w, acc[i][3]);
                acc[i][4] = fmaf(xm[i], w1.x, acc[i][4]);
                acc[i][5] = fmaf(xm[i], w1.y, acc[i][5]);
                acc[i][6] = fmaf(xm[i], w1.z, acc[i][6]);
                acc[i][7] = fmaf(xm[i], w1.w, acc[i][7]);
            }
        }
        #pragma unroll
        for (int i = 0; i < 10; i++) {
            int row = ty + 8*i;
            if (row < T_) {
                float* o = outb + row * NC + col;
                *reinterpret_cast<float4*>(o)       = make_float4(acc[i][0], acc[i][1], acc[i][2], acc[i][3]);
                *reinterpret_cast<float4*>(o + 128) = make_float4(acc[i][4], acc[i][5], acc[i][6], acc[i][7]);
            }
        }
    } else {
        // gk: tx 0..20 -> cols 4tx..4tx+3 of 84 ; Co: tx 21..27 -> cols 4(tx-21)..+3 of 28
        if (tx < 28) {
            const bool isgk   = (tx < 21);
            const float* W    = isgk ? gk : Co;
            const int stride  = isgk ? 84 : 28;
            const int col     = isgk ? 4 * tx : 4 * (tx - 21);
            const int ocol    = isgk ? 512 + col : 596 + col;
            float acc[10][4];
            #pragma unroll
            for (int i = 0; i < 10; i++) {
                #pragma unroll
                for (int j = 0; j < 4; j++) acc[i][j] = isgk ? gbias[col + j] : 0.0f;
            }
            #pragma unroll 2
            for (int k = 0; k < D_; k++) {
                float4 w = *reinterpret_cast<const float4*>(&W[k * stride + col]);
                float xm[10];
                #pragma unroll
                for (int i = 0; i < 10; i++) xm[i] = xs[(ty + 8*i) * D_ + k];
                #pragma unroll
                for (int i = 0; i < 10; i++) {
                    acc[i][0] = fmaf(xm[i], w.x, acc[i][0]);
                    acc[i][1] = fmaf(xm[i], w.y, acc[i][1]);
                    acc[i][2] = fmaf(xm[i], w.z, acc[i][2]);
                    acc[i][3] = fmaf(xm[i], w.w, acc[i][3]);
                }
            }
            #pragma unroll
            for (int i = 0; i < 10; i++) {
                int row = ty + 8*i;
                if (row < T_) {
                    *reinterpret_cast<float4*>(outb + row * NC + ocol) =
                        make_float4(acc[i][0], acc[i][1], acc[i][2], acc[i][3]);
                }
            }
        }
    }
}

// ---------------------------------------------------------------------------
// Recurrence kernel: 128 CTAs x 576 threads, 227712 B dynamic smem.
// smem layout (float offsets):
//   uah   [75][512]  @ 0
//   xgc   [75][112]  @ 38400   (cols 0..83 = XG', 84..111 = XC)
//   wab   [28][256]  @ 46800   (bf16x2, Wa packed pairs along D)
//   va    [512]      @ 53968
//   ba1   [512]      @ 54480
//   uo    [784]      @ 54992
//   was   [512]      @ 55776
//   sc    [80]       @ 56288
//   smw   [80]       @ 56368
//   xmc   [112]      @ 56448
//   hm    [88]       @ 56560
//   st    [32]       @ 56648
//   pr    [32]       @ 56680
//   woy   [32]       @ 56712
//   uoh   [32]       @ 56744
//   lut   [32]       @ 56776
//   b1    [88]       @ 56808
//   bo    [32]       @ 56896
// total 56928 floats = 227712 B
// ---------------------------------------------------------------------------
#define SMEM_FLOATS 56928

__global__ void __launch_bounds__(576)
recur_kernel(const float* __restrict__ Wa,
             const float* __restrict__ Va,
             const float* __restrict__ Ba1,
             const float* __restrict__ grk,
             const float* __restrict__ gbias,
             const float* __restrict__ Wo,
             const float* __restrict__ Uo,
             const float* __restrict__ Bo,
             const float* __restrict__ emb,
             float* __restrict__ out)
{
    extern __shared__ float smem[];
    float*        uah  = smem;
    float*        xgc  = smem + 38400;
    unsigned int* wab  = reinterpret_cast<unsigned int*>(smem + 46800);
    float*        va_s = smem + 53968;
    float*        ba1_s= smem + 54480;
    float*        uo_s = smem + 54992;
    float*        was_s= smem + 55776;
    float*        sc_s = smem + 56288;
    float*        smw_s= smem + 56368;
    float*        xmc_s= smem + 56448;
    float*        hm_s = smem + 56560;
    float*        st_s = smem + 56648;
    float*        pr_s = smem + 56680;
    float*        woy_s= smem + 56712;
    float*        uoh_s= smem + 56744;
    float*        lut_s= smem + 56776;
    float*        b1_s = smem + 56808;
    float*        bo_s = smem + 56896;

    const int tid  = threadIdx.x;
    const int b    = blockIdx.x;
    const int lane = tid & 31;
    const int wid  = tid >> 5;

    // ---- bulk load precomputed UaH / XGC from scratch ----
    const float4* src = reinterpret_cast<const float4*>(g_scr + (long)b * PT);
    for (int i = tid; i < PT/4; i += 576) {
        float4 v = src[i];
        int base = i * 4;
        int t = base / NC;
        int c = base - t * NC;
        float* dst = (c < 512) ? &uah[t * 512 + c] : &xgc[t * 112 + (c - 512)];
        *reinterpret_cast<float4*>(dst) = v;
    }
    // ---- params ----
    for (int i = tid; i < 512; i += 576) { va_s[i] = Va[i]; ba1_s[i] = Ba1[i]; }
    for (int i = tid; i < 784; i += 576) uo_s[i] = Uo[i];
    for (int i = tid; i < 28*256; i += 576) {
        int r = i >> 8, c = i & 255;
        __nv_bfloat162 h;
        h.x = __float2bfloat16_rn(Wa[r * 512 + 2*c]);
        h.y = __float2bfloat16_rn(Wa[r * 512 + 2*c + 1]);
        wab[i] = *reinterpret_cast<unsigned int*>(&h);
    }
    if (tid < 84) b1_s[tid] = gbias[84 + tid];
    if (tid < 28) {
        bo_s[tid] = Bo[tid];
        float a = 0.0f;
        #pragma unroll
        for (int j = 0; j < 28; j++) a = fmaf(emb[tid * 28 + j], Wo[j], a);
        lut_s[tid] = a;
    }
    if (tid < 32) { st_s[tid] = 0.0f; pr_s[tid] = 0.0f; }
    __syncthreads();

    float va_r[16];
    #pragma unroll
    for (int i = 0; i < 16; i++) va_r[i] = va_s[lane + 32*i];

    float* outb = out + (long)b * T_ * V_;

    for (int t = 0; t < T_; t++) {
        // ---------- Phase A: state-only work, split across warps ----------
        if (tid < 256) {
            // WaS[2*tid], WaS[2*tid+1]
            float2 a = *reinterpret_cast<const float2*>(&ba1_s[2*tid]);
            #pragma unroll
            for (int v = 0; v < 28; v++) {
                float s = st_s[v];
                __nv_bfloat162 h = *reinterpret_cast<__nv_bfloat162*>(&wab[v * 256 + tid]);
                a.x = fmaf(s, __bfloat162float(h.x), a.x);
                a.y = fmaf(s, __bfloat162float(h.y), a.y);
            }
            *reinterpret_cast<float2*>(&was_s[2*tid]) = a;
        } else if (wid == 8) {
            if (lane < 28) {
                float a = 0.0f;
                #pragma unroll
                for (int u = 0; u < 28; u++) a = fmaf(st_s[u], uo_s[u * 28 + lane], a);
                uoh_s[lane] = a;
            }
        } else if (wid == 9) {
            if (lane < 28) {
                int ix = (int)pr_s[lane];
                ix = max(0, min(27, ix));
                woy_s[lane] = lut_s[ix];
            }
        } else if (tid >= 448 && tid < 532) {
            int g = tid - 448;
            float a = b1_s[g];
            #pragma unroll
            for (int v = 0; v < 28; v++) a = fmaf(st_s[v], grk[v * 84 + g], a);
            hm_s[g] = a;
        }
        __syncthreads();

        // ---------- Phase B: attention scores (dominant: 2 MUFU/elem) ----------
        float ws_r[16];
        #pragma unroll
        for (int i = 0; i < 16; i++) ws_r[i] = was_s[lane + 32*i];

        for (int r = wid; r < T_; r += 18) {
            const float* up = &uah[r * 512];
            float acc0 = 0.0f, acc1 = 0.0f;
            #pragma unroll
            for (int i = 0; i < 16; i += 2) {
                {
                    float a  = up[lane + 32*i] + ws_r[i];
                    float e  = ex2f(a * (2.0f * L2E));
                    float rc = rcpf(e + 1.0f);
                    acc0 = fmaf(fmaf(-2.0f, rc, 1.0f), va_r[i], acc0);
                }
                {
                    float a  = up[lane + 32*(i+1)] + ws_r[i+1];
                    float e  = ex2f(a * (2.0f * L2E));
                    float rc = rcpf(e + 1.0f);
                    acc1 = fmaf(fmaf(-2.0f, rc, 1.0f), va_r[i+1], acc1);
                }
            }
            float acc = acc0 + acc1;
            #pragma unroll
            for (int o = 16; o; o >>= 1) acc += __shfl_xor_sync(0xffffffffu, acc, o);
            if (lane == 0) sc_s[r] = acc;
        }
        __syncthreads();

        // ---------- softmax over t (warp 0) ----------
        if (wid == 0) {
            float s0 = sc_s[lane];
            float s1 = sc_s[lane + 32];
            float s2 = (lane < 11) ? sc_s[lane + 64] : -3.0e38f;
            float m = fmaxf(fmaxf(s0, s1), s2);
            #pragma unroll
            for (int o = 16; o; o >>= 1) m = fmaxf(m, __shfl_xor_sync(0xffffffffu, m, o));
            float e0 = ex2f((s0 - m) * L2E);
            float e1 = ex2f((s1 - m) * L2E);
            float e2 = (lane < 11) ? ex2f((s2 - m) * L2E) : 0.0f;
            float sum = e0 + e1 + e2;
            #pragma unroll
            for (int o = 16; o; o >>= 1) sum += __shfl_xor_sync(0xffffffffu, sum, o);
            float inv = rcpf(sum);
            smw_s[lane]      = e0 * inv;
            smw_s[lane + 32] = e1 * inv;
            if (lane < 11) smw_s[lane + 64] = e2 * inv;
        }
        __syncthreads();

        // ---------- Phase C: xm / CoC = sm . XGC  (112 cols) ----------
        if (tid < 112) {
            float a0 = 0.0f, a1 = 0.0f, a2 = 0.0f, a3 = 0.0f;
            #pragma unroll 4
            for (int k = 0; k < 72; k += 4) {
                a0 = fmaf(smw_s[k],     xgc[(k    ) * 112 + tid], a0);
                a1 = fmaf(smw_s[k + 1], xgc[(k + 1) * 112 + tid], a1);
                a2 = fmaf(smw_s[k + 2], xgc[(k + 2) * 112 + tid], a2);
                a3 = fmaf(smw_s[k + 3], xgc[(k + 3) * 112 + tid], a3);
            }
            a0 = fmaf(smw_s[72], xgc[72 * 112 + tid], a0);
            a1 = fmaf(smw_s[73], xgc[73 * 112 + tid], a1);
            a2 = fmaf(smw_s[74], xgc[74 * 112 + tid], a2);
            xmc_s[tid] = (a0 + a1) + (a2 + a3);
        }
        __syncthreads();

        // ---------- Phase D: GRU gates + output softmax (warp 0) ----------
        if (wid == 0) {
            int v = lane;
            float logit = -3.0e38f;
            float ns = 0.0f;
            if (v < 28) {
                float xz = xmc_s[v],      xr = xmc_s[28 + v], xh  = xmc_s[56 + v];
                float hz = hm_s[v],       hr = hm_s[28 + v],  hh_ = hm_s[56 + v];
                float z  = fast_sig(xz + hz);
                float r  = fast_sig(xr + hr);
                float hh = fast_tanh(fmaf(r, hh_, xh));
                float st = st_s[v];
                ns = fmaf(z, st - hh, hh);
                logit = ((woy_s[v] + uoh_s[v]) + (xmc_s[84 + v] + bo_s[v]));
            }
            float m = logit;
            #pragma unroll
            for (int o = 16; o; o >>= 1) m = fmaxf(m, __shfl_xor_sync(0xffffffffu, m, o));
            float e = (v < 28) ? ex2f((logit - m) * L2E) : 0.0f;
            float sum = e;
            #pragma unroll
            for (int o = 16; o; o >>= 1) sum += __shfl_xor_sync(0xffffffffu, sum, o);
            float p = e * rcpf(sum);
            if (v < 28) {
                st_s[v] = ns;
                pr_s[v] = p;
                outb[t * V_ + v] = p;
            }
        }
        __syncthreads();
    }
}

// ---------------------------------------------------------------------------
extern "C" void kernel_launch(void* const* d_in, const int* in_sizes, int n_in,
                              void* d_out, int out_size)
{
    const float* x    = (const float*)d_in[0];
    const float* Wa   = (const float*)d_in[1];
    const float* Ua   = (const float*)d_in[2];
    const float* Va   = (const float*)d_in[3];
    const float* Ba1  = (const float*)d_in[4];
    const float* Ba2  = (const float*)d_in[5];
    /* Ba3 (d_in[6]) is softmax-invariant: skipped */
    const float* gk   = (const float*)d_in[7];
    const float* grk  = (const float*)d_in[8];
    const float* gb   = (const float*)d_in[9];
    const float* Wo   = (const float*)d_in[10];
    const float* Uo   = (const float*)d_in[11];
    const float* Co   = (const float*)d_in[12];
    const float* Bo   = (const float*)d_in[13];
    const float* emb  = (const float*)d_in[14];
    float* out = (float*)d_out;

    cudaFuncSetAttribute(prologue_kernel, cudaFuncAttributeMaxDynamicSharedMemorySize, 80 * 512 * 4);
    cudaFuncSetAttribute(recur_kernel,    cudaFuncAttributeMaxDynamicSharedMemorySize, SMEM_FLOATS * 4);

    dim3 pg(B_, 3);
    prologue_kernel<<<pg, 256, 80 * 512 * 4>>>(x, Ua, gk, Co, Ba2, gb);
    recur_kernel<<<B_, 576, SMEM_FLOATS * 4>>>(Wa, Va, Ba1, grk, gb, Wo, Uo, Bo, emb, out);
}

// round 4
// speedup vs baseline: 1.5530x; 1.5530x over previous
#include <cuda_runtime.h>
#include <cuda_bf16.h>

// ---------------------------------------------------------------------------
// CascadedAttention: B=128, T=75, D=512, V=28
// Kernel 1 (prologue): per-batch GEMM [75,512] @ [512, 512+84+28] -> scratch
// Kernel 2 (recurrence): 1 CTA per batch row, smem-resident, 75 steps.
// ---------------------------------------------------------------------------

#define B_  128
#define T_  75
#define D_  512
#define V_  28
#define NC  624
#define PT  (T_*NC)          // 46800 floats per batch row

__device__ float g_scr[B_ * PT];   // 23.96 MB static scratch (no allocation)

__device__ __forceinline__ float ex2f(float x){ float y; asm("ex2.approx.f32 %0, %1;" : "=f"(y) : "f"(x)); return y; }
__device__ __forceinline__ float rcpf(float x){ float y; asm("rcp.approx.f32 %0, %1;" : "=f"(y) : "f"(x)); return y; }
__device__ __forceinline__ float tanhf_hw(float x){ float y; asm("tanh.approx.f32 %0, %1;" : "=f"(y) : "f"(x)); return y; }
#define L2E 1.4426950408889634f
__device__ __forceinline__ float fast_sig(float x){ return fmaf(0.5f, tanhf_hw(0.5f * x), 0.5f); }

// ---------------------------------------------------------------------------
// Prologue GEMM (unchanged from R2 — known good).
// grid (128, 3), 256 threads = 32 tx * 8 ty.
// ---------------------------------------------------------------------------
__global__ void __launch_bounds__(256)
prologue_kernel(const float* __restrict__ x,
                const float* __restrict__ Ua,
                const float* __restrict__ gk,
                const float* __restrict__ Co,
                const float* __restrict__ Ba2,
                const float* __restrict__ gbias)
{
    extern __shared__ float xs[];          // [80][512]
    const int b    = blockIdx.x;
    const int part = blockIdx.y;
    const int tid  = threadIdx.x;
    const int tx   = tid & 31;
    const int ty   = tid >> 5;

    const float4* xb = reinterpret_cast<const float4*>(x + (long)b * T_ * D_);
    for (int i = tid; i < T_ * (D_/4); i += 256) {
        float4 v = xb[i];
        int t = i >> 7;
        int k = (i & 127) << 2;
        float* d = &xs[t * D_ + k];
        d[0]=v.x; d[1]=v.y; d[2]=v.z; d[3]=v.w;
    }
    for (int i = tid; i < 5 * D_; i += 256) xs[T_ * D_ + i] = 0.0f;
    __syncthreads();

    float* outb = g_scr + (long)b * PT;

    if (part < 2) {
        const int col = part * 256 + 4 * tx;
        float acc[10][8];
        #pragma unroll
        for (int i = 0; i < 10; i++) {
            #pragma unroll
            for (int j = 0; j < 4; j++) { acc[i][j] = Ba2[col + j]; acc[i][4+j] = Ba2[col + 128 + j]; }
        }
        #pragma unroll 2
        for (int k = 0; k < D_; k++) {
            float4 w0 = *reinterpret_cast<const float4*>(&Ua[k * D_ + col]);
            float4 w1 = *reinterpret_cast<const float4*>(&Ua[k * D_ + col + 128]);
            float xm[10];
            #pragma unroll
            for (int i = 0; i < 10; i++) xm[i] = xs[(ty + 8*i) * D_ + k];
            #pragma unroll
            for (int i = 0; i < 10; i++) {
                acc[i][0] = fmaf(xm[i], w0.x, acc[i][0]);
                acc[i][1] = fmaf(xm[i], w0.y, acc[i][1]);
                acc[i][2] = fmaf(xm[i], w0.z, acc[i][2]);
                acc[i][3] = fmaf(xm[i], w0.w, acc[i][3]);
                acc[i][4] = fmaf(xm[i], w1.x, acc[i][4]);
                acc[i][5] = fmaf(xm[i], w1.y, acc[i][5]);
                acc[i][6] = fmaf(xm[i], w1.z, acc[i][6]);
                acc[i][7] = fmaf(xm[i], w1.w, acc[i][7]);
            }
        }
        #pragma unroll
        for (int i = 0; i < 10; i++) {
            int row = ty + 8*i;
            if (row < T_) {
                float* o = outb + row * NC + col;
                *reinterpret_cast<float4*>(o)       = make_float4(acc[i][0], acc[i][1], acc[i][2], acc[i][3]);
                *reinterpret_cast<float4*>(o + 128) = make_float4(acc[i][4], acc[i][5], acc[i][6], acc[i][7]);
            }
        }
    } else {
        if (tx < 28) {
            const bool isgk   = (tx < 21);
            const float* W    = isgk ? gk : Co;
            const int stride  = isgk ? 84 : 28;
            const int col     = isgk ? 4 * tx : 4 * (tx - 21);
            const int ocol    = isgk ? 512 + col : 596 + col;
            float acc[10][4];
            #pragma unroll
            for (int i = 0; i < 10; i++) {
                #pragma unroll
                for (int j = 0; j < 4; j++) acc[i][j] = isgk ? gbias[col + j] : 0.0f;
            }
            #pragma unroll 2
            for (int k = 0; k < D_; k++) {
                float4 w = *reinterpret_cast<const float4*>(&W[k * stride + col]);
                float xm[10];
                #pragma unroll
                for (int i = 0; i < 10; i++) xm[i] = xs[(ty + 8*i) * D_ + k];
                #pragma unroll
                for (int i = 0; i < 10; i++) {
                    acc[i][0] = fmaf(xm[i], w.x, acc[i][0]);
                    acc[i][1] = fmaf(xm[i], w.y, acc[i][1]);
                    acc[i][2] = fmaf(xm[i], w.z, acc[i][2]);
                    acc[i][3] = fmaf(xm[i], w.w, acc[i][3]);
                }
            }
            #pragma unroll
            for (int i = 0; i < 10; i++) {
                int row = ty + 8*i;
                if (row < T_) {
                    *reinterpret_cast<float4*>(outb + row * NC + ocol) =
                        make_float4(acc[i][0], acc[i][1], acc[i][2], acc[i][3]);
                }
            }
        }
    }
}

// ---------------------------------------------------------------------------
// Recurrence kernel v2: 128 CTAs x 576 threads, 227712 B dynamic smem.
// Step pipeline (4 barriers):
//   A: warps 0-7 -> WaS ; warps 8-10 -> hm ; warp 11 -> uoh ; warp 12 -> woy
//   B: all 18 warps -> scores via tanh.approx (1 MUFU/elem)
//   C: warps 0-3 -> in-register softmax over t + sm.XGC (shfl broadcast)
//   D: warp 0 -> GRU gates + output softmax
// ---------------------------------------------------------------------------
#define SMEM_FLOATS 56928

__global__ void __launch_bounds__(576)
recur_kernel(const float* __restrict__ Wa,
             const float* __restrict__ Va,
             const float* __restrict__ Ba1,
             const float* __restrict__ grk,
             const float* __restrict__ gbias,
             const float* __restrict__ Wo,
             const float* __restrict__ Uo,
             const float* __restrict__ Bo,
             const float* __restrict__ emb,
             float* __restrict__ out)
{
    extern __shared__ float smem[];
    float*        uah  = smem;                 // [75][512]
    float*        xgc  = smem + 38400;         // [75][112]
    unsigned int* wab  = reinterpret_cast<unsigned int*>(smem + 46800); // [28][256] bf16x2
    float*        va_s = smem + 53968;
    float*        ba1_s= smem + 54480;
    float*        uo_s = smem + 54992;
    float*        was_s= smem + 55776;
    float*        sc_s = smem + 56288;
    float*        xmc_s= smem + 56448;
    float*        hm_s = smem + 56560;
    float*        st_s = smem + 56648;
    float*        pr_s = smem + 56680;
    float*        woy_s= smem + 56712;
    float*        uoh_s= smem + 56744;
    float*        lut_s= smem + 56776;
    float*        b1_s = smem + 56808;
    float*        bo_s = smem + 56896;

    const int tid  = threadIdx.x;
    const int b    = blockIdx.x;
    const int lane = tid & 31;
    const int wid  = tid >> 5;

    // ---- bulk load precomputed UaH / XGC from scratch ----
    const float4* src = reinterpret_cast<const float4*>(g_scr + (long)b * PT);
    for (int i = tid; i < PT/4; i += 576) {
        float4 v = src[i];
        int base = i * 4;
        int t = base / NC;
        int c = base - t * NC;
        float* dst = (c < 512) ? &uah[t * 512 + c] : &xgc[t * 112 + (c - 512)];
        *reinterpret_cast<float4*>(dst) = v;
    }
    // ---- params ----
    for (int i = tid; i < 512; i += 576) { va_s[i] = Va[i]; ba1_s[i] = Ba1[i]; }
    for (int i = tid; i < 784; i += 576) uo_s[i] = Uo[i];
    for (int i = tid; i < 28*256; i += 576) {
        int r = i >> 8, c = i & 255;
        __nv_bfloat162 h;
        h.x = __float2bfloat16_rn(Wa[r * 512 + 2*c]);
        h.y = __float2bfloat16_rn(Wa[r * 512 + 2*c + 1]);
        wab[i] = *reinterpret_cast<unsigned int*>(&h);
    }
    if (tid < 84) b1_s[tid] = gbias[84 + tid];
    if (tid < 28) {
        bo_s[tid] = Bo[tid];
        float a = 0.0f;
        #pragma unroll
        for (int j = 0; j < 28; j++) a = fmaf(emb[tid * 28 + j], Wo[j], a);
        lut_s[tid] = a;
    }
    if (tid < 32) { st_s[tid] = 0.0f; pr_s[tid] = 0.0f; }
    __syncthreads();

    float va_r[16];
    #pragma unroll
    for (int i = 0; i < 16; i++) va_r[i] = va_s[lane + 32*i];

    float* outb = out + (long)b * T_ * V_;

    for (int t = 0; t < T_; t++) {
        // ---------- Phase A: state-only GEMVs, all in parallel ----------
        if (tid < 256) {
            // WaS[2*tid], WaS[2*tid+1]
            float2 a = *reinterpret_cast<const float2*>(&ba1_s[2*tid]);
            #pragma unroll
            for (int v = 0; v < 28; v++) {
                float s = st_s[v];
                unsigned int w = wab[v * 256 + tid];
                float wx = __int_as_float(w << 16);
                float wy = __int_as_float(w & 0xffff0000u);
                a.x = fmaf(s, wx, a.x);
                a.y = fmaf(s, wy, a.y);
            }
            *reinterpret_cast<float2*>(&was_s[2*tid]) = a;
        } else if (tid < 340) {
            int g = tid - 256;              // hm: 84 outputs
            float a = b1_s[g];
            #pragma unroll
            for (int v = 0; v < 28; v++) a = fmaf(st_s[v], grk[v * 84 + g], a);
            hm_s[g] = a;
        } else if (wid == 11) {
            if (lane < 28) {                // uoh
                float a = 0.0f;
                #pragma unroll
                for (int u = 0; u < 28; u++) a = fmaf(st_s[u], uo_s[u * 28 + lane], a);
                uoh_s[lane] = a;
            }
        } else if (wid == 12) {
            if (lane < 28) {                // woy (embedding LUT on int(prev_pred))
                int ix = (int)pr_s[lane];
                ix = max(0, min(27, ix));
                woy_s[lane] = lut_s[ix];
            }
        }
        __syncthreads();

        // ---------- Phase B: scores, 18 warps, tanh.approx ----------
        {
            float ws_r[16];
            #pragma unroll
            for (int i = 0; i < 16; i++) ws_r[i] = was_s[lane + 32*i];

            for (int r = wid; r < T_; r += 18) {
                const float* up = &uah[r * 512];
                float acc0 = 0.0f, acc1 = 0.0f;
                #pragma unroll
                for (int i = 0; i < 16; i += 2) {
                    float th0 = tanhf_hw(up[lane + 32*i]     + ws_r[i]);
                    float th1 = tanhf_hw(up[lane + 32*(i+1)] + ws_r[i+1]);
                    acc0 = fmaf(th0, va_r[i],   acc0);
                    acc1 = fmaf(th1, va_r[i+1], acc1);
                }
                float acc = acc0 + acc1;
                #pragma unroll
                for (int o = 16; o; o >>= 1) acc += __shfl_xor_sync(0xffffffffu, acc, o);
                if (lane == 0) sc_s[r] = acc;
            }
        }
        __syncthreads();

        // ---------- Phase C: softmax-in-registers + sm.XGC (warps 0-3) ----------
        if (wid < 4) {
            float s0 = sc_s[lane];
            float s1 = sc_s[lane + 32];
            float s2 = (lane < 11) ? sc_s[lane + 64] : -3.0e38f;
            float m = fmaxf(fmaxf(s0, s1), s2);
            #pragma unroll
            for (int o = 16; o; o >>= 1) m = fmaxf(m, __shfl_xor_sync(0xffffffffu, m, o));
            float e0 = ex2f((s0 - m) * L2E);
            float e1 = ex2f((s1 - m) * L2E);
            float e2 = (lane < 11) ? ex2f((s2 - m) * L2E) : 0.0f;
            float sum = e0 + e1 + e2;
            #pragma unroll
            for (int o = 16; o; o >>= 1) sum += __shfl_xor_sync(0xffffffffu, sum, o);
            float inv = rcpf(sum);

            int c = wid * 28 + ((lane < 28) ? lane : 0);   // 112 cols; lanes 28-31 duplicate
            float a0 = 0.0f, a1 = 0.0f, a2 = 0.0f, a3 = 0.0f;
            #pragma unroll
            for (int k = 0; k < 75; k += 4) {
                float w0 = __shfl_sync(0xffffffffu, (k      < 32) ? e0 : ((k      < 64) ? e1 : e2), k      & 31);
                a0 = fmaf(w0, xgc[k * 112 + c], a0);
                if (k + 1 < 75) {
                    float w1 = __shfl_sync(0xffffffffu, (k+1 < 32) ? e0 : ((k+1 < 64) ? e1 : e2), (k+1) & 31);
                    a1 = fmaf(w1, xgc[(k+1) * 112 + c], a1);
                }
                if (k + 2 < 75) {
                    float w2 = __shfl_sync(0xffffffffu, (k+2 < 32) ? e0 : ((k+2 < 64) ? e1 : e2), (k+2) & 31);
                    a2 = fmaf(w2, xgc[(k+2) * 112 + c], a2);
                }
                if (k + 3 < 75) {
                    float w3 = __shfl_sync(0xffffffffu, (k+3 < 32) ? e0 : ((k+3 < 64) ? e1 : e2), (k+3) & 31);
                    a3 = fmaf(w3, xgc[(k+3) * 112 + c], a3);
                }
            }
            if (lane < 28) xmc_s[c] = ((a0 + a1) + (a2 + a3)) * inv;
        }
        __syncthreads();

        // ---------- Phase D: GRU gates + output softmax (warp 0) ----------
        if (wid == 0) {
            int v = lane;
            float logit = -3.0e38f;
            float ns = 0.0f;
            if (v < 28) {
                float xz = xmc_s[v],      xr = xmc_s[28 + v], xh  = xmc_s[56 + v];
                float hz = hm_s[v],       hr = hm_s[28 + v],  hh_ = hm_s[56 + v];
                float z  = fast_sig(xz + hz);
                float r  = fast_sig(xr + hr);
                float hh = tanhf_hw(fmaf(r, hh_, xh));
                float st = st_s[v];
                ns = fmaf(z, st - hh, hh);
                logit = ((woy_s[v] + uoh_s[v]) + (xmc_s[84 + v] + bo_s[v]));
            }
            float m = logit;
            #pragma unroll
            for (int o = 16; o; o >>= 1) m = fmaxf(m, __shfl_xor_sync(0xffffffffu, m, o));
            float e = (v < 28) ? ex2f((logit - m) * L2E) : 0.0f;
            float sum = e;
            #pragma unroll
            for (int o = 16; o; o >>= 1) sum += __shfl_xor_sync(0xffffffffu, sum, o);
            float p = e * rcpf(sum);
            if (v < 28) {
                st_s[v] = ns;
                pr_s[v] = p;
                outb[t * V_ + v] = p;
            }
        }
        __syncthreads();
    }
}

// ---------------------------------------------------------------------------
extern "C" void kernel_launch(void* const* d_in, const int* in_sizes, int n_in,
                              void* d_out, int out_size)
{
    const float* x    = (const float*)d_in[0];
    const float* Wa   = (const float*)d_in[1];
    const float* Ua   = (const float*)d_in[2];
    const float* Va   = (const float*)d_in[3];
    const float* Ba1  = (const float*)d_in[4];
    const float* Ba2  = (const float*)d_in[5];
    /* Ba3 (d_in[6]) is softmax-invariant: skipped */
    const float* gk   = (const float*)d_in[7];
    const float* grk  = (const float*)d_in[8];
    const float* gb   = (const float*)d_in[9];
    const float* Wo   = (const float*)d_in[10];
    const float* Uo   = (const float*)d_in[11];
    const float* Co   = (const float*)d_in[12];
    const float* Bo   = (const float*)d_in[13];
    const float* emb  = (const float*)d_in[14];
    float* out = (float*)d_out;

    cudaFuncSetAttribute(prologue_kernel, cudaFuncAttributeMaxDynamicSharedMemorySize, 80 * 512 * 4);
    cudaFuncSetAttribute(recur_kernel,    cudaFuncAttributeMaxDynamicSharedMemorySize, SMEM_FLOATS * 4);

    dim3 pg(B_, 3);
    prologue_kernel<<<pg, 256, 80 * 512 * 4>>>(x, Ua, gk, Co, Ba2, gb);
    recur_kernel<<<B_, 576, SMEM_FLOATS * 4>>>(Wa, Va, Ba1, grk, gb, Wo, Uo, Bo, emb, out);
}